// round 8
// baseline (speedup 1.0000x reference)
#include <cuda_runtime.h>
#include <cstdint>

#define IN_DIM 512
#define HID    512
#define OUT_DIM 256
#define TSTEPS 16
#define M_MAX  32768
#define HL_PITCH 576   // hlist row pitch, mult of 8 -> 1152 B, mult of 16

// Scratch (device globals - allocation-free rule)
__device__ float          g_pre1[(size_t)M_MAX * HID];
__device__ __align__(16) unsigned short g_hlist[(size_t)M_MAX * HL_PITCH];
__device__ unsigned short g_offs[(size_t)M_MAX * 17];

__device__ __forceinline__ void dup2(unsigned long long& d, float s)
{
    asm("mov.b64 %0, {%1, %1};" : "=l"(d) : "f"(s));
}
__device__ __forceinline__ void fma2(unsigned long long& acc,
                                     unsigned long long a, unsigned long long b)
{
    asm("fma.rn.f32x2 %0, %1, %2, %0;" : "+l"(acc) : "l"(a), "l"(b));
}
__device__ __forceinline__ void addx2(unsigned long long& a, unsigned long long w)
{
    asm("add.rn.f32x2 %0, %0, %1;" : "+l"(a) : "l"(w));
}

// ---------------------------------------------------------------------------
// Kernel 1: pre1[m][n] = sum_k x[m][k] * W1[n][k] + b1[n]
// Tile 128M x 256N per block, 256 threads, 8Mx16N per thread, KC=8 double-buf.
// (unchanged from round 7)
// ---------------------------------------------------------------------------
#define KC 8
#define SPA 132   // A smem pitch
#define SPB 260   // B smem pitch
__global__ void __launch_bounds__(256, 1) gemm1_kernel(
    const float* __restrict__ A,   // x  [M][512]
    const float* __restrict__ W1,  // W1 [512][512] (n-major)
    const float* __restrict__ b1)
{
    __shared__ float As[2][KC][SPA];
    __shared__ float Bs[2][KC][SPB];

    const int tid  = threadIdx.x;
    const int lane = tid & 31;
    const int warp = tid >> 5;
    const int bm   = blockIdx.x * 128;
    const int bn   = blockIdx.y * 256;

    const int lm = lane >> 3;   // 0..3
    const int ln = lane & 7;    // 0..7
    const int row0 = (warp & 3) * 32 + lm * 8;
    const int nhalf = (warp >> 2) * 128;

    const int arow = tid >> 1;
    const int ak4  = (tid & 1) * 4;

    const float* Ag  = A  + (size_t)(bm + arow)       * IN_DIM + ak4;
    const float* Bg0 = W1 + (size_t)(bn + arow)       * IN_DIM + ak4;
    const float* Bg1 = W1 + (size_t)(bn + arow + 128) * IN_DIM + ak4;

    unsigned long long accp[8][8];
#pragma unroll
    for (int i = 0; i < 8; i++)
#pragma unroll
        for (int j = 0; j < 8; j++) accp[i][j] = 0ull;

    float4 pa, pb0, pb1;

    pa  = *(const float4*)(Ag);
    pb0 = *(const float4*)(Bg0);
    pb1 = *(const float4*)(Bg1);
    {
        As[0][ak4+0][arow] = pa.x;  As[0][ak4+1][arow] = pa.y;
        As[0][ak4+2][arow] = pa.z;  As[0][ak4+3][arow] = pa.w;
        Bs[0][ak4+0][arow] = pb0.x; Bs[0][ak4+1][arow] = pb0.y;
        Bs[0][ak4+2][arow] = pb0.z; Bs[0][ak4+3][arow] = pb0.w;
        Bs[0][ak4+0][arow+128] = pb1.x; Bs[0][ak4+1][arow+128] = pb1.y;
        Bs[0][ak4+2][arow+128] = pb1.z; Bs[0][ak4+3][arow+128] = pb1.w;
    }
    __syncthreads();

    int cur = 0;
    for (int k0 = 0; k0 < IN_DIM; k0 += KC) {
        const int nk = k0 + KC;
        if (nk < IN_DIM) {
            pa  = *(const float4*)(Ag  + nk);
            pb0 = *(const float4*)(Bg0 + nk);
            pb1 = *(const float4*)(Bg1 + nk);
        }
#pragma unroll
        for (int kk = 0; kk < KC; kk++) {
            float4 a0 = *(const float4*)&As[cur][kk][row0];
            float4 a1 = *(const float4*)&As[cur][kk][row0 + 4];
            unsigned long long bq[8];
#pragma unroll
            for (int q = 0; q < 4; q++) {
                ulonglong2 bl = *(const ulonglong2*)&Bs[cur][kk][nhalf + q * 32 + ln * 4];
                bq[2*q]   = bl.x;
                bq[2*q+1] = bl.y;
            }
            unsigned long long av2[8];
            dup2(av2[0], a0.x); dup2(av2[1], a0.y);
            dup2(av2[2], a0.z); dup2(av2[3], a0.w);
            dup2(av2[4], a1.x); dup2(av2[5], a1.y);
            dup2(av2[6], a1.z); dup2(av2[7], a1.w);
#pragma unroll
            for (int i = 0; i < 8; i++)
#pragma unroll
                for (int j = 0; j < 8; j++)
                    fma2(accp[i][j], av2[i], bq[j]);
        }
        if (nk < IN_DIM) {
            const int nxt = cur ^ 1;
            As[nxt][ak4+0][arow] = pa.x;  As[nxt][ak4+1][arow] = pa.y;
            As[nxt][ak4+2][arow] = pa.z;  As[nxt][ak4+3][arow] = pa.w;
            Bs[nxt][ak4+0][arow] = pb0.x; Bs[nxt][ak4+1][arow] = pb0.y;
            Bs[nxt][ak4+2][arow] = pb0.z; Bs[nxt][ak4+3][arow] = pb0.w;
            Bs[nxt][ak4+0][arow+128] = pb1.x; Bs[nxt][ak4+1][arow+128] = pb1.y;
            Bs[nxt][ak4+2][arow+128] = pb1.z; Bs[nxt][ak4+3][arow+128] = pb1.w;
            __syncthreads();
            cur = nxt;
        }
    }

#pragma unroll
    for (int q = 0; q < 4; q++) {
        const int colq = nhalf + q * 32 + ln * 4;
        const float4 bb = *(const float4*)&b1[bn + colq];
#pragma unroll
        for (int i = 0; i < 8; i++) {
            union { unsigned long long u; float2 f; } c0, c1;
            c0.u = accp[i][2*q];
            c1.u = accp[i][2*q+1];
            float4 o = make_float4(c0.f.x + bb.x, c0.f.y + bb.y,
                                   c1.f.x + bb.z, c1.f.y + bb.w);
            *(float4*)(g_pre1 + (size_t)(bm + row0 + i) * HID + bn + colq) = o;
        }
    }
}

// ---------------------------------------------------------------------------
// Kernel 2: (unchanged) 4 rows/block, match-based counting sort, buckets
// padded to multiples of 4 (pad index = 512 -> zero row in phase2's W2Ts).
// ---------------------------------------------------------------------------
#define BK_ROWS 4
__global__ void __launch_bounds__(512) bucketize_kernel()
{
    const int h    = threadIdx.x;
    const int lane = h & 31;
    const int warp = h >> 5;
    const int row_base = blockIdx.x * BK_ROWS;

    float p[BK_ROWS];
#pragma unroll
    for (int r = 0; r < BK_ROWS; r++)
        p[r] = g_pre1[(size_t)(row_base + r) * HID + h];

    __shared__ int wcnt[16][17];
    __shared__ int wpre[16][17];
    __shared__ int tot[17];
    __shared__ int base[18];

#pragma unroll
    for (int r = 0; r < BK_ROWS; r++) {
        const int row = row_base + r;

        int k = 0;
        float m = 0.f;
#pragma unroll
        for (int t = 1; t <= TSTEPS; t++) {
            m += p[r];
            if (m > 0.5f) { k = t; break; }
        }

        __syncthreads();
        if (threadIdx.x < 16 * 17) ((int*)wcnt)[threadIdx.x] = 0;
        __syncthreads();

        unsigned peers = __match_any_sync(0xffffffffu, k);
        int rank = __popc(peers & ((1u << lane) - 1u));
        if (rank == 0) wcnt[warp][k] = __popc(peers);
        __syncthreads();

        if (threadIdx.x < 17) {
            int b = threadIdx.x;
            int s = 0;
#pragma unroll
            for (int w = 0; w < 16; w++) { wpre[w][b] = s; s += wcnt[w][b]; }
            tot[b] = s;
        }
        __syncthreads();

        if (warp == 0) {
            int sz = 0;
            if (lane < 16) sz = (tot[lane + 1] + 3) & ~3;
            int s = sz;
#pragma unroll
            for (int d = 1; d < 16; d <<= 1) {
                int t = __shfl_up_sync(0xffffffffu, s, d);
                if (lane >= d) s += t;
            }
            if (lane < 16) base[lane + 1] = s - sz;
            if (lane == 15) base[17] = s;
        }
        __syncthreads();

        unsigned short* hrow = g_hlist + (size_t)row * HL_PITCH;
        if (k > 0) {
            int pos = base[k] + wpre[warp][k] + rank;
            hrow[pos] = (unsigned short)h;
        }
        if (threadIdx.x < 16) {
            int b = threadIdx.x + 1;
            int sz = tot[b];
            int pad = (sz + 3) & ~3;
            for (int q = sz; q < pad; q++) hrow[base[b] + q] = 512;
        }
        if (threadIdx.x < 16)
            g_offs[(size_t)row * 17 + threadIdx.x + 1] = (unsigned short)base[threadIdx.x + 2];
        if (threadIdx.x == 16)
            g_offs[(size_t)row * 17] = 0;
    }
}

// ---------------------------------------------------------------------------
// Kernel 3: warp-per-row 4-wide packed gather. Pitch 64: every W2Ts row is
// 128B-aligned -> each warp gather = exactly 2 LDS wavefronts (was 3 @ p66).
// Staging is oo-major to keep STS conflict-free at pitch 64.
// ---------------------------------------------------------------------------
#define W2T_PITCH 64
#define W2T_ROWS  513
#define W2T_BYTES (W2T_ROWS * W2T_PITCH * 4)   // 131328, mult of 16
#define ROWS_PER_ITER 16
#define ROWS_PER_BLOCK 128
#define P2_SMEM_BYTES (W2T_BYTES + ROWS_PER_ITER * HL_PITCH * 2 + ROWS_PER_ITER * 17 * 2)

__global__ void __launch_bounds__(512) phase2_kernel(
    const float* __restrict__ W2,  // [256][512]
    const float* __restrict__ b2,  // [256]
    float* __restrict__ out)       // [M][256]
{
    extern __shared__ char smem_raw[];
    float* W2Ts = (float*)smem_raw;                                     // [513][64]
    unsigned short* lists = (unsigned short*)(smem_raw + W2T_BYTES);    // [16][576]
    unsigned short* soffs = (unsigned short*)(smem_raw + W2T_BYTES
                                              + ROWS_PER_ITER * HL_PITCH * 2);

    const int tid    = threadIdx.x;
    const int w      = tid >> 5;
    const int lane   = tid & 31;
    const int o2     = lane * 2;
    const int o_base = blockIdx.y * 64;

    // Stage W2^T slice, oo-major: lanes write consecutive oo -> conflict-free
    // STS at pitch 64. LDG is lane-stride-512 (W2 is L2-resident after wave 1).
    for (int i = tid; i < 64 * 512; i += 512) {
        int oo = i & 63;
        int hh = i >> 6;
        W2Ts[hh * W2T_PITCH + oo] = W2[(size_t)(o_base + oo) * HID + hh];
    }
    if (tid < 64) W2Ts[512 * W2T_PITCH + tid] = 0.f;

    const float2 bb = *(const float2*)&b2[o_base + o2];
    const int row0 = blockIdx.x * ROWS_PER_BLOCK;

    for (int r0 = row0; r0 < row0 + ROWS_PER_BLOCK; r0 += ROWS_PER_ITER) {
        __syncthreads();
        {
            const uint4* src = (const uint4*)(g_hlist + (size_t)r0 * HL_PITCH);
            uint4* dst = (uint4*)lists;
            for (int i = tid; i < (ROWS_PER_ITER * HL_PITCH) / 8; i += 512) dst[i] = src[i];
        }
        if (tid < ROWS_PER_ITER * 17)
            soffs[tid] = g_offs[(size_t)r0 * 17 + tid];
        __syncthreads();

        const unsigned short* mylist = lists + w * HL_PITCH;
        const unsigned short* myoff  = soffs + w * 17;
        const float* W2o = W2Ts + o2;

        float2 Ck[16];
        int idx = 0;
#pragma unroll
        for (int k = 1; k <= TSTEPS; k++) {
            const int e = myoff[k];
            unsigned long long accA = 0ull, accB = 0ull;
            for (; idx < e; idx += 4) {
                uint2 pk = *(const uint2*)&mylist[idx];
                int h0 = pk.x & 0xFFFF;
                int h1 = pk.x >> 16;
                int h2 = pk.y & 0xFFFF;
                int h3 = pk.y >> 16;
                unsigned long long w0 = *(const unsigned long long*)&W2o[h0 * W2T_PITCH];
                unsigned long long w1 = *(const unsigned long long*)&W2o[h1 * W2T_PITCH];
                unsigned long long w2 = *(const unsigned long long*)&W2o[h2 * W2T_PITCH];
                unsigned long long w3 = *(const unsigned long long*)&W2o[h3 * W2T_PITCH];
                addx2(accA, w0);
                addx2(accB, w1);
                addx2(accA, w2);
                addx2(accB, w3);
            }
            addx2(accA, accB);
            union { unsigned long long u; float2 f; } cvt;
            cvt.u = accA;
            Ck[k - 1] = cvt.f;
        }

        float m2x = 0.f, m2y = 0.f, scx = 0.f, scy = 0.f;
#pragma unroll
        for (int t = 1; t <= TSTEPS; t++) {
            float yx = 0.f, yy = 0.f;
#pragma unroll
            for (int d = 1; d <= TSTEPS; d++)
                if (t % d == 0) { yx += Ck[d - 1].x; yy += Ck[d - 1].y; }
            m2x = (m2x + yx) + bb.x;
            m2y = (m2y + yy) + bb.y;
            if (m2x > 0.5f) { scx += 1.f; m2x = 0.f; }
            if (m2y > 0.5f) { scy += 1.f; m2y = 0.f; }
        }
        float2 res = make_float2(scx * 0.0625f, scy * 0.0625f);
        *(float2*)&out[(size_t)(r0 + w) * OUT_DIM + o_base + o2] = res;
    }
}

// ---------------------------------------------------------------------------
extern "C" void kernel_launch(void* const* d_in, const int* in_sizes, int n_in,
                              void* d_out, int out_size)
{
    const float* x  = (const float*)d_in[0];
    const float* W1 = (const float*)d_in[1];
    const float* b1 = (const float*)d_in[2];
    const float* W2 = (const float*)d_in[3];
    const float* b2 = (const float*)d_in[4];
    float* out = (float*)d_out;

    const int M = in_sizes[0] / IN_DIM;  // 32768

    dim3 g1(M / 128, HID / 256);
    gemm1_kernel<<<g1, 256>>>(x, W1, b1);

    bucketize_kernel<<<M / BK_ROWS, 512>>>();

    cudaFuncSetAttribute(phase2_kernel,
                         cudaFuncAttributeMaxDynamicSharedMemorySize,
                         P2_SMEM_BYTES);
    dim3 g2(M / ROWS_PER_BLOCK, OUT_DIM / 64);
    phase2_kernel<<<g2, 512, P2_SMEM_BYTES>>>(W2, b2, out);
}

// round 9
// speedup vs baseline: 1.1067x; 1.1067x over previous
#include <cuda_runtime.h>
#include <cstdint>

#define IN_DIM 512
#define HID    512
#define OUT_DIM 256
#define TSTEPS 16
#define M_MAX  32768
#define HL_PITCH 576   // hlist row pitch, mult of 8 -> 1152 B, mult of 16

// Scratch (device globals - allocation-free rule)
__device__ float          g_pre1[(size_t)M_MAX * HID];
__device__ __align__(16) unsigned short g_hlist[(size_t)M_MAX * HL_PITCH];
__device__ unsigned short g_offs[(size_t)M_MAX * 17];

__device__ __forceinline__ void dup2(unsigned long long& d, float s)
{
    asm("mov.b64 %0, {%1, %1};" : "=l"(d) : "f"(s));
}
__device__ __forceinline__ void fma2(unsigned long long& acc,
                                     unsigned long long a, unsigned long long b)
{
    asm("fma.rn.f32x2 %0, %1, %2, %0;" : "+l"(acc) : "l"(a), "l"(b));
}
__device__ __forceinline__ void addx2(unsigned long long& a, unsigned long long w)
{
    asm("add.rn.f32x2 %0, %0, %1;" : "+l"(a) : "l"(w));
}

// ---------------------------------------------------------------------------
// Kernel 1: pre1[m][n] = sum_k x[m][k] * W1[n][k] + b1[n]
// Tile 128M x 256N per block, 256 threads, 8Mx16N per thread, KC=8 double-buf.
// (unchanged)
// ---------------------------------------------------------------------------
#define KC 8
#define SPA 132   // A smem pitch
#define SPB 260   // B smem pitch
__global__ void __launch_bounds__(256, 1) gemm1_kernel(
    const float* __restrict__ A,   // x  [M][512]
    const float* __restrict__ W1,  // W1 [512][512] (n-major)
    const float* __restrict__ b1)
{
    __shared__ float As[2][KC][SPA];
    __shared__ float Bs[2][KC][SPB];

    const int tid  = threadIdx.x;
    const int lane = tid & 31;
    const int warp = tid >> 5;
    const int bm   = blockIdx.x * 128;
    const int bn   = blockIdx.y * 256;

    const int lm = lane >> 3;   // 0..3
    const int ln = lane & 7;    // 0..7
    const int row0 = (warp & 3) * 32 + lm * 8;
    const int nhalf = (warp >> 2) * 128;

    const int arow = tid >> 1;
    const int ak4  = (tid & 1) * 4;

    const float* Ag  = A  + (size_t)(bm + arow)       * IN_DIM + ak4;
    const float* Bg0 = W1 + (size_t)(bn + arow)       * IN_DIM + ak4;
    const float* Bg1 = W1 + (size_t)(bn + arow + 128) * IN_DIM + ak4;

    unsigned long long accp[8][8];
#pragma unroll
    for (int i = 0; i < 8; i++)
#pragma unroll
        for (int j = 0; j < 8; j++) accp[i][j] = 0ull;

    float4 pa, pb0, pb1;

    pa  = *(const float4*)(Ag);
    pb0 = *(const float4*)(Bg0);
    pb1 = *(const float4*)(Bg1);
    {
        As[0][ak4+0][arow] = pa.x;  As[0][ak4+1][arow] = pa.y;
        As[0][ak4+2][arow] = pa.z;  As[0][ak4+3][arow] = pa.w;
        Bs[0][ak4+0][arow] = pb0.x; Bs[0][ak4+1][arow] = pb0.y;
        Bs[0][ak4+2][arow] = pb0.z; Bs[0][ak4+3][arow] = pb0.w;
        Bs[0][ak4+0][arow+128] = pb1.x; Bs[0][ak4+1][arow+128] = pb1.y;
        Bs[0][ak4+2][arow+128] = pb1.z; Bs[0][ak4+3][arow+128] = pb1.w;
    }
    __syncthreads();

    int cur = 0;
    for (int k0 = 0; k0 < IN_DIM; k0 += KC) {
        const int nk = k0 + KC;
        if (nk < IN_DIM) {
            pa  = *(const float4*)(Ag  + nk);
            pb0 = *(const float4*)(Bg0 + nk);
            pb1 = *(const float4*)(Bg1 + nk);
        }
#pragma unroll
        for (int kk = 0; kk < KC; kk++) {
            float4 a0 = *(const float4*)&As[cur][kk][row0];
            float4 a1 = *(const float4*)&As[cur][kk][row0 + 4];
            unsigned long long bq[8];
#pragma unroll
            for (int q = 0; q < 4; q++) {
                ulonglong2 bl = *(const ulonglong2*)&Bs[cur][kk][nhalf + q * 32 + ln * 4];
                bq[2*q]   = bl.x;
                bq[2*q+1] = bl.y;
            }
            unsigned long long av2[8];
            dup2(av2[0], a0.x); dup2(av2[1], a0.y);
            dup2(av2[2], a0.z); dup2(av2[3], a0.w);
            dup2(av2[4], a1.x); dup2(av2[5], a1.y);
            dup2(av2[6], a1.z); dup2(av2[7], a1.w);
#pragma unroll
            for (int i = 0; i < 8; i++)
#pragma unroll
                for (int j = 0; j < 8; j++)
                    fma2(accp[i][j], av2[i], bq[j]);
        }
        if (nk < IN_DIM) {
            const int nxt = cur ^ 1;
            As[nxt][ak4+0][arow] = pa.x;  As[nxt][ak4+1][arow] = pa.y;
            As[nxt][ak4+2][arow] = pa.z;  As[nxt][ak4+3][arow] = pa.w;
            Bs[nxt][ak4+0][arow] = pb0.x; Bs[nxt][ak4+1][arow] = pb0.y;
            Bs[nxt][ak4+2][arow] = pb0.z; Bs[nxt][ak4+3][arow] = pb0.w;
            Bs[nxt][ak4+0][arow+128] = pb1.x; Bs[nxt][ak4+1][arow+128] = pb1.y;
            Bs[nxt][ak4+2][arow+128] = pb1.z; Bs[nxt][ak4+3][arow+128] = pb1.w;
            __syncthreads();
            cur = nxt;
        }
    }

#pragma unroll
    for (int q = 0; q < 4; q++) {
        const int colq = nhalf + q * 32 + ln * 4;
        const float4 bb = *(const float4*)&b1[bn + colq];
#pragma unroll
        for (int i = 0; i < 8; i++) {
            union { unsigned long long u; float2 f; } c0, c1;
            c0.u = accp[i][2*q];
            c1.u = accp[i][2*q+1];
            float4 o = make_float4(c0.f.x + bb.x, c0.f.y + bb.y,
                                   c1.f.x + bb.z, c1.f.y + bb.w);
            *(float4*)(g_pre1 + (size_t)(bm + row0 + i) * HID + bn + colq) = o;
        }
    }
}

// ---------------------------------------------------------------------------
// Kernel 2: (unchanged) 4 rows/block, match-based counting sort, buckets
// padded to multiples of 4 (pad index = 512 -> zero row in phase2's W2Ts).
// ---------------------------------------------------------------------------
#define BK_ROWS 4
__global__ void __launch_bounds__(512) bucketize_kernel()
{
    const int h    = threadIdx.x;
    const int lane = h & 31;
    const int warp = h >> 5;
    const int row_base = blockIdx.x * BK_ROWS;

    float p[BK_ROWS];
#pragma unroll
    for (int r = 0; r < BK_ROWS; r++)
        p[r] = g_pre1[(size_t)(row_base + r) * HID + h];

    __shared__ int wcnt[16][17];
    __shared__ int wpre[16][17];
    __shared__ int tot[17];
    __shared__ int base[18];

#pragma unroll
    for (int r = 0; r < BK_ROWS; r++) {
        const int row = row_base + r;

        int k = 0;
        float m = 0.f;
#pragma unroll
        for (int t = 1; t <= TSTEPS; t++) {
            m += p[r];
            if (m > 0.5f) { k = t; break; }
        }

        __syncthreads();
        if (threadIdx.x < 16 * 17) ((int*)wcnt)[threadIdx.x] = 0;
        __syncthreads();

        unsigned peers = __match_any_sync(0xffffffffu, k);
        int rank = __popc(peers & ((1u << lane) - 1u));
        if (rank == 0) wcnt[warp][k] = __popc(peers);
        __syncthreads();

        if (threadIdx.x < 17) {
            int b = threadIdx.x;
            int s = 0;
#pragma unroll
            for (int w = 0; w < 16; w++) { wpre[w][b] = s; s += wcnt[w][b]; }
            tot[b] = s;
        }
        __syncthreads();

        if (warp == 0) {
            int sz = 0;
            if (lane < 16) sz = (tot[lane + 1] + 3) & ~3;
            int s = sz;
#pragma unroll
            for (int d = 1; d < 16; d <<= 1) {
                int t = __shfl_up_sync(0xffffffffu, s, d);
                if (lane >= d) s += t;
            }
            if (lane < 16) base[lane + 1] = s - sz;
            if (lane == 15) base[17] = s;
        }
        __syncthreads();

        unsigned short* hrow = g_hlist + (size_t)row * HL_PITCH;
        if (k > 0) {
            int pos = base[k] + wpre[warp][k] + rank;
            hrow[pos] = (unsigned short)h;
        }
        if (threadIdx.x < 16) {
            int b = threadIdx.x + 1;
            int sz = tot[b];
            int pad = (sz + 3) & ~3;
            for (int q = sz; q < pad; q++) hrow[base[b] + q] = 512;
        }
        if (threadIdx.x < 16)
            g_offs[(size_t)row * 17 + threadIdx.x + 1] = (unsigned short)base[threadIdx.x + 2];
        if (threadIdx.x == 16)
            g_offs[(size_t)row * 17] = 0;
    }
}

// ---------------------------------------------------------------------------
// Kernel 3: warp-per-row 4-wide packed gather at ALIGNED pitch 64
// (2 LDS wavefronts per gather). Staging via per-warp 32x33 tiled transpose:
// coalesced LDG -> conflict-free STS -> stride-33 LDS -> contiguous STS.
// ---------------------------------------------------------------------------
#define W2T_PITCH 64
#define W2T_ROWS  513
#define W2T_BYTES (W2T_ROWS * W2T_PITCH * 4)   // 131328, mult of 16
#define TT_BYTES  (16 * 32 * 33 * 4)           // 67584, per-warp transpose tiles
#define ROWS_PER_ITER 16
#define ROWS_PER_BLOCK 128
#define P2_SMEM_BYTES (W2T_BYTES + TT_BYTES + ROWS_PER_ITER * HL_PITCH * 2 + ROWS_PER_ITER * 17 * 2)

__global__ void __launch_bounds__(512) phase2_kernel(
    const float* __restrict__ W2,  // [256][512]
    const float* __restrict__ b2,  // [256]
    float* __restrict__ out)       // [M][256]
{
    extern __shared__ char smem_raw[];
    float* W2Ts = (float*)smem_raw;                                     // [513][64]
    float* TT   = (float*)(smem_raw + W2T_BYTES);                       // [16][32][33]
    unsigned short* lists = (unsigned short*)(smem_raw + W2T_BYTES + TT_BYTES); // [16][576]
    unsigned short* soffs = (unsigned short*)(smem_raw + W2T_BYTES + TT_BYTES
                                              + ROWS_PER_ITER * HL_PITCH * 2);

    const int tid    = threadIdx.x;
    const int w      = tid >> 5;
    const int lane   = tid & 31;
    const int o2     = lane * 2;
    const int o_base = blockIdx.y * 64;

    // --- Stage W2^T via tiled transpose: 32 tiles (2 oo-blocks x 16 hh-blocks),
    // warp w handles tiles t = w and w+16.
    {
        float* tile = TT + w * 32 * 33;
#pragma unroll
        for (int tt = 0; tt < 2; tt++) {
            const int t   = w + tt * 16;
            const int oo0 = (t & 1) * 32;
            const int hh0 = (t >> 1) * 32;
            // load 32 rows of W2 (each row: 32 consecutive hh) - coalesced
#pragma unroll
            for (int r = 0; r < 32; r++) {
                tile[r * 33 + lane] =
                    W2[(size_t)(o_base + oo0 + r) * HID + hh0 + lane];
            }
            __syncwarp();
            // write transposed: dest row hh0+r2, col oo0+lane
#pragma unroll
            for (int r2 = 0; r2 < 32; r2++) {
                W2Ts[(hh0 + r2) * W2T_PITCH + oo0 + lane] = tile[lane * 33 + r2];
            }
            __syncwarp();
        }
    }
    if (tid < 64) W2Ts[512 * W2T_PITCH + tid] = 0.f;

    const float2 bb = *(const float2*)&b2[o_base + o2];
    const int row0 = blockIdx.x * ROWS_PER_BLOCK;

    for (int r0 = row0; r0 < row0 + ROWS_PER_BLOCK; r0 += ROWS_PER_ITER) {
        __syncthreads();
        {
            const uint4* src = (const uint4*)(g_hlist + (size_t)r0 * HL_PITCH);
            uint4* dst = (uint4*)lists;
            for (int i = tid; i < (ROWS_PER_ITER * HL_PITCH) / 8; i += 512) dst[i] = src[i];
        }
        if (tid < ROWS_PER_ITER * 17)
            soffs[tid] = g_offs[(size_t)r0 * 17 + tid];
        __syncthreads();

        const unsigned short* mylist = lists + w * HL_PITCH;
        const unsigned short* myoff  = soffs + w * 17;
        const float* W2o = W2Ts + o2;

        float2 Ck[16];
        int idx = 0;
#pragma unroll
        for (int k = 1; k <= TSTEPS; k++) {
            const int e = myoff[k];
            unsigned long long accA = 0ull, accB = 0ull;
            for (; idx < e; idx += 4) {
                uint2 pk = *(const uint2*)&mylist[idx];
                int h0 = pk.x & 0xFFFF;
                int h1 = pk.x >> 16;
                int h2 = pk.y & 0xFFFF;
                int h3 = pk.y >> 16;
                unsigned long long w0 = *(const unsigned long long*)&W2o[h0 * W2T_PITCH];
                unsigned long long w1 = *(const unsigned long long*)&W2o[h1 * W2T_PITCH];
                unsigned long long w2 = *(const unsigned long long*)&W2o[h2 * W2T_PITCH];
                unsigned long long w3 = *(const unsigned long long*)&W2o[h3 * W2T_PITCH];
                addx2(accA, w0);
                addx2(accB, w1);
                addx2(accA, w2);
                addx2(accB, w3);
            }
            addx2(accA, accB);
            union { unsigned long long u; float2 f; } cvt;
            cvt.u = accA;
            Ck[k - 1] = cvt.f;
        }

        float m2x = 0.f, m2y = 0.f, scx = 0.f, scy = 0.f;
#pragma unroll
        for (int t = 1; t <= TSTEPS; t++) {
            float yx = 0.f, yy = 0.f;
#pragma unroll
            for (int d = 1; d <= TSTEPS; d++)
                if (t % d == 0) { yx += Ck[d - 1].x; yy += Ck[d - 1].y; }
            m2x = (m2x + yx) + bb.x;
            m2y = (m2y + yy) + bb.y;
            if (m2x > 0.5f) { scx += 1.f; m2x = 0.f; }
            if (m2y > 0.5f) { scy += 1.f; m2y = 0.f; }
        }
        float2 res = make_float2(scx * 0.0625f, scy * 0.0625f);
        *(float2*)&out[(size_t)(r0 + w) * OUT_DIM + o_base + o2] = res;
    }
}

// ---------------------------------------------------------------------------
extern "C" void kernel_launch(void* const* d_in, const int* in_sizes, int n_in,
                              void* d_out, int out_size)
{
    const float* x  = (const float*)d_in[0];
    const float* W1 = (const float*)d_in[1];
    const float* b1 = (const float*)d_in[2];
    const float* W2 = (const float*)d_in[3];
    const float* b2 = (const float*)d_in[4];
    float* out = (float*)d_out;

    const int M = in_sizes[0] / IN_DIM;  // 32768

    dim3 g1(M / 128, HID / 256);
    gemm1_kernel<<<g1, 256>>>(x, W1, b1);

    bucketize_kernel<<<M / BK_ROWS, 512>>>();

    cudaFuncSetAttribute(phase2_kernel,
                         cudaFuncAttributeMaxDynamicSharedMemorySize,
                         P2_SMEM_BYTES);
    dim3 g2(M / ROWS_PER_BLOCK, OUT_DIM / 64);
    phase2_kernel<<<g2, 512, P2_SMEM_BYTES>>>(W2, b2, out);
}

// round 10
// speedup vs baseline: 1.2139x; 1.0969x over previous
#include <cuda_runtime.h>
#include <cstdint>

#define IN_DIM 512
#define HID    512
#define OUT_DIM 256
#define TSTEPS 16
#define M_MAX  32768
#define HL_PITCH 576   // hlist row pitch, mult of 8 -> 1152 B, mult of 16

// Scratch (device globals - allocation-free rule)
__device__ float          g_pre1[(size_t)M_MAX * HID];
__device__ __align__(16) unsigned short g_hlist[(size_t)M_MAX * HL_PITCH];
__device__ unsigned short g_offs[(size_t)M_MAX * 17];

__device__ __forceinline__ void dup2(unsigned long long& d, float s)
{
    asm("mov.b64 %0, {%1, %1};" : "=l"(d) : "f"(s));
}
__device__ __forceinline__ void fma2(unsigned long long& acc,
                                     unsigned long long a, unsigned long long b)
{
    asm("fma.rn.f32x2 %0, %1, %2, %0;" : "+l"(acc) : "l"(a), "l"(b));
}
__device__ __forceinline__ void addx2(unsigned long long& a, unsigned long long w)
{
    asm("add.rn.f32x2 %0, %0, %1;" : "+l"(a) : "l"(w));
}

// ---------------------------------------------------------------------------
// Kernel 1: pre1[m][n] = sum_k x[m][k] * W1[n][k] + b1[n]
// Tile 128M x 256N per block, 256 threads, 8Mx16N per thread, KC=8 double-buf.
// (unchanged)
// ---------------------------------------------------------------------------
#define KC 8
#define SPA 132   // A smem pitch
#define SPB 260   // B smem pitch
__global__ void __launch_bounds__(256, 1) gemm1_kernel(
    const float* __restrict__ A,   // x  [M][512]
    const float* __restrict__ W1,  // W1 [512][512] (n-major)
    const float* __restrict__ b1)
{
    __shared__ float As[2][KC][SPA];
    __shared__ float Bs[2][KC][SPB];

    const int tid  = threadIdx.x;
    const int lane = tid & 31;
    const int warp = tid >> 5;
    const int bm   = blockIdx.x * 128;
    const int bn   = blockIdx.y * 256;

    const int lm = lane >> 3;   // 0..3
    const int ln = lane & 7;    // 0..7
    const int row0 = (warp & 3) * 32 + lm * 8;
    const int nhalf = (warp >> 2) * 128;

    const int arow = tid >> 1;
    const int ak4  = (tid & 1) * 4;

    const float* Ag  = A  + (size_t)(bm + arow)       * IN_DIM + ak4;
    const float* Bg0 = W1 + (size_t)(bn + arow)       * IN_DIM + ak4;
    const float* Bg1 = W1 + (size_t)(bn + arow + 128) * IN_DIM + ak4;

    unsigned long long accp[8][8];
#pragma unroll
    for (int i = 0; i < 8; i++)
#pragma unroll
        for (int j = 0; j < 8; j++) accp[i][j] = 0ull;

    float4 pa, pb0, pb1;

    pa  = *(const float4*)(Ag);
    pb0 = *(const float4*)(Bg0);
    pb1 = *(const float4*)(Bg1);
    {
        As[0][ak4+0][arow] = pa.x;  As[0][ak4+1][arow] = pa.y;
        As[0][ak4+2][arow] = pa.z;  As[0][ak4+3][arow] = pa.w;
        Bs[0][ak4+0][arow] = pb0.x; Bs[0][ak4+1][arow] = pb0.y;
        Bs[0][ak4+2][arow] = pb0.z; Bs[0][ak4+3][arow] = pb0.w;
        Bs[0][ak4+0][arow+128] = pb1.x; Bs[0][ak4+1][arow+128] = pb1.y;
        Bs[0][ak4+2][arow+128] = pb1.z; Bs[0][ak4+3][arow+128] = pb1.w;
    }
    __syncthreads();

    int cur = 0;
    for (int k0 = 0; k0 < IN_DIM; k0 += KC) {
        const int nk = k0 + KC;
        if (nk < IN_DIM) {
            pa  = *(const float4*)(Ag  + nk);
            pb0 = *(const float4*)(Bg0 + nk);
            pb1 = *(const float4*)(Bg1 + nk);
        }
#pragma unroll
        for (int kk = 0; kk < KC; kk++) {
            float4 a0 = *(const float4*)&As[cur][kk][row0];
            float4 a1 = *(const float4*)&As[cur][kk][row0 + 4];
            unsigned long long bq[8];
#pragma unroll
            for (int q = 0; q < 4; q++) {
                ulonglong2 bl = *(const ulonglong2*)&Bs[cur][kk][nhalf + q * 32 + ln * 4];
                bq[2*q]   = bl.x;
                bq[2*q+1] = bl.y;
            }
            unsigned long long av2[8];
            dup2(av2[0], a0.x); dup2(av2[1], a0.y);
            dup2(av2[2], a0.z); dup2(av2[3], a0.w);
            dup2(av2[4], a1.x); dup2(av2[5], a1.y);
            dup2(av2[6], a1.z); dup2(av2[7], a1.w);
#pragma unroll
            for (int i = 0; i < 8; i++)
#pragma unroll
                for (int j = 0; j < 8; j++)
                    fma2(accp[i][j], av2[i], bq[j]);
        }
        if (nk < IN_DIM) {
            const int nxt = cur ^ 1;
            As[nxt][ak4+0][arow] = pa.x;  As[nxt][ak4+1][arow] = pa.y;
            As[nxt][ak4+2][arow] = pa.z;  As[nxt][ak4+3][arow] = pa.w;
            Bs[nxt][ak4+0][arow] = pb0.x; Bs[nxt][ak4+1][arow] = pb0.y;
            Bs[nxt][ak4+2][arow] = pb0.z; Bs[nxt][ak4+3][arow] = pb0.w;
            Bs[nxt][ak4+0][arow+128] = pb1.x; Bs[nxt][ak4+1][arow+128] = pb1.y;
            Bs[nxt][ak4+2][arow+128] = pb1.z; Bs[nxt][ak4+3][arow+128] = pb1.w;
            __syncthreads();
            cur = nxt;
        }
    }

#pragma unroll
    for (int q = 0; q < 4; q++) {
        const int colq = nhalf + q * 32 + ln * 4;
        const float4 bb = *(const float4*)&b1[bn + colq];
#pragma unroll
        for (int i = 0; i < 8; i++) {
            union { unsigned long long u; float2 f; } c0, c1;
            c0.u = accp[i][2*q];
            c1.u = accp[i][2*q+1];
            float4 o = make_float4(c0.f.x + bb.x, c0.f.y + bb.y,
                                   c1.f.x + bb.z, c1.f.y + bb.w);
            *(float4*)(g_pre1 + (size_t)(bm + row0 + i) * HID + bn + colq) = o;
        }
    }
}

// ---------------------------------------------------------------------------
// Kernel 2: (unchanged) 4 rows/block, match-based counting sort, buckets
// padded to multiples of 4 (pad index = 512 -> zero row in phase2's W2Ts).
// ---------------------------------------------------------------------------
#define BK_ROWS 4
__global__ void __launch_bounds__(512) bucketize_kernel()
{
    const int h    = threadIdx.x;
    const int lane = h & 31;
    const int warp = h >> 5;
    const int row_base = blockIdx.x * BK_ROWS;

    float p[BK_ROWS];
#pragma unroll
    for (int r = 0; r < BK_ROWS; r++)
        p[r] = g_pre1[(size_t)(row_base + r) * HID + h];

    __shared__ int wcnt[16][17];
    __shared__ int wpre[16][17];
    __shared__ int tot[17];
    __shared__ int base[18];

#pragma unroll
    for (int r = 0; r < BK_ROWS; r++) {
        const int row = row_base + r;

        int k = 0;
        float m = 0.f;
#pragma unroll
        for (int t = 1; t <= TSTEPS; t++) {
            m += p[r];
            if (m > 0.5f) { k = t; break; }
        }

        __syncthreads();
        if (threadIdx.x < 16 * 17) ((int*)wcnt)[threadIdx.x] = 0;
        __syncthreads();

        unsigned peers = __match_any_sync(0xffffffffu, k);
        int rank = __popc(peers & ((1u << lane) - 1u));
        if (rank == 0) wcnt[warp][k] = __popc(peers);
        __syncthreads();

        if (threadIdx.x < 17) {
            int b = threadIdx.x;
            int s = 0;
#pragma unroll
            for (int w = 0; w < 16; w++) { wpre[w][b] = s; s += wcnt[w][b]; }
            tot[b] = s;
        }
        __syncthreads();

        if (warp == 0) {
            int sz = 0;
            if (lane < 16) sz = (tot[lane + 1] + 3) & ~3;
            int s = sz;
#pragma unroll
            for (int d = 1; d < 16; d <<= 1) {
                int t = __shfl_up_sync(0xffffffffu, s, d);
                if (lane >= d) s += t;
            }
            if (lane < 16) base[lane + 1] = s - sz;
            if (lane == 15) base[17] = s;
        }
        __syncthreads();

        unsigned short* hrow = g_hlist + (size_t)row * HL_PITCH;
        if (k > 0) {
            int pos = base[k] + wpre[warp][k] + rank;
            hrow[pos] = (unsigned short)h;
        }
        if (threadIdx.x < 16) {
            int b = threadIdx.x + 1;
            int sz = tot[b];
            int pad = (sz + 3) & ~3;
            for (int q = sz; q < pad; q++) hrow[base[b] + q] = 512;
        }
        if (threadIdx.x < 16)
            g_offs[(size_t)row * 17 + threadIdx.x + 1] = (unsigned short)base[threadIdx.x + 2];
        if (threadIdx.x == 16)
            g_offs[(size_t)row * 17] = 0;
    }
}

// ---------------------------------------------------------------------------
// Kernel 3: 1024 threads / 32 warps (8 per SMSP) to cover LDS latency chains.
// 32 rows per iteration, warp-per-row 4-wide packed gather at pitch 64.
// TT (transpose scratch) unioned with lists buffer (disjoint lifetimes).
// ---------------------------------------------------------------------------
#define W2T_PITCH 64
#define W2T_ROWS  513
#define W2T_BYTES (W2T_ROWS * W2T_PITCH * 4)   // 131328, mult of 16
#define ROWS_PER_ITER 32
#define ROWS_PER_BLOCK 128
#define TT_BYTES     (16 * 32 * 33 * 4)                     // 67584
#define LISTS_BYTES  (ROWS_PER_ITER * HL_PITCH * 2)         // 36864
#define UNION_BYTES  (TT_BYTES > (LISTS_BYTES + ROWS_PER_ITER*17*2) ? \
                      TT_BYTES : (LISTS_BYTES + ROWS_PER_ITER*17*2))
#define P2_SMEM_BYTES (W2T_BYTES + UNION_BYTES)

__global__ void __launch_bounds__(1024, 1) phase2_kernel(
    const float* __restrict__ W2,  // [256][512]
    const float* __restrict__ b2,  // [256]
    float* __restrict__ out)       // [M][256]
{
    extern __shared__ char smem_raw[];
    float* W2Ts = (float*)smem_raw;                                   // [513][64]
    float* TT   = (float*)(smem_raw + W2T_BYTES);                     // staging only
    unsigned short* lists = (unsigned short*)(smem_raw + W2T_BYTES);  // [32][576]
    unsigned short* soffs = (unsigned short*)(smem_raw + W2T_BYTES + LISTS_BYTES);

    const int tid    = threadIdx.x;
    const int w      = tid >> 5;       // 0..31
    const int lane   = tid & 31;
    const int o2     = lane * 2;
    const int o_base = blockIdx.y * 64;

    // --- Stage W2^T via tiled transpose (warps 0..15; TT region is reused
    // as `lists` after the first __syncthreads below).
    if (w < 16) {
        float* tile = TT + w * 32 * 33;
#pragma unroll
        for (int tt = 0; tt < 2; tt++) {
            const int t   = w + tt * 16;
            const int oo0 = (t & 1) * 32;
            const int hh0 = (t >> 1) * 32;
#pragma unroll
            for (int r = 0; r < 32; r++) {
                tile[r * 33 + lane] =
                    W2[(size_t)(o_base + oo0 + r) * HID + hh0 + lane];
            }
            __syncwarp();
#pragma unroll
            for (int r2 = 0; r2 < 32; r2++) {
                W2Ts[(hh0 + r2) * W2T_PITCH + oo0 + lane] = tile[lane * 33 + r2];
            }
            __syncwarp();
        }
    }
    if (tid < 64) W2Ts[512 * W2T_PITCH + tid] = 0.f;

    const float2 bb = *(const float2*)&b2[o_base + o2];
    const int row0 = blockIdx.x * ROWS_PER_BLOCK;

    for (int r0 = row0; r0 < row0 + ROWS_PER_BLOCK; r0 += ROWS_PER_ITER) {
        __syncthreads();   // staging/prev-iter readers done
        {
            const uint4* src = (const uint4*)(g_hlist + (size_t)r0 * HL_PITCH);
            uint4* dst = (uint4*)lists;
            // 32*576 ushorts = 36864 B = 2304 uint4
            for (int i = tid; i < (ROWS_PER_ITER * HL_PITCH) / 8; i += 1024) dst[i] = src[i];
        }
        if (tid < ROWS_PER_ITER * 17)
            soffs[tid] = g_offs[(size_t)r0 * 17 + tid];
        __syncthreads();

        const unsigned short* mylist = lists + w * HL_PITCH;
        const unsigned short* myoff  = soffs + w * 17;
        const float* W2o = W2Ts + o2;

        float2 Ck[16];
        int idx = 0;
#pragma unroll
        for (int k = 1; k <= TSTEPS; k++) {
            const int e = myoff[k];
            unsigned long long accA = 0ull, accB = 0ull;
            for (; idx < e; idx += 4) {
                uint2 pk = *(const uint2*)&mylist[idx];
                int h0 = pk.x & 0xFFFF;
                int h1 = pk.x >> 16;
                int h2 = pk.y & 0xFFFF;
                int h3 = pk.y >> 16;
                unsigned long long w0 = *(const unsigned long long*)&W2o[h0 * W2T_PITCH];
                unsigned long long w1 = *(const unsigned long long*)&W2o[h1 * W2T_PITCH];
                unsigned long long w2 = *(const unsigned long long*)&W2o[h2 * W2T_PITCH];
                unsigned long long w3 = *(const unsigned long long*)&W2o[h3 * W2T_PITCH];
                addx2(accA, w0);
                addx2(accB, w1);
                addx2(accA, w2);
                addx2(accB, w3);
            }
            addx2(accA, accB);
            union { unsigned long long u; float2 f; } cvt;
            cvt.u = accA;
            Ck[k - 1] = cvt.f;
        }

        float m2x = 0.f, m2y = 0.f, scx = 0.f, scy = 0.f;
#pragma unroll
        for (int t = 1; t <= TSTEPS; t++) {
            float yx = 0.f, yy = 0.f;
#pragma unroll
            for (int d = 1; d <= TSTEPS; d++)
                if (t % d == 0) { yx += Ck[d - 1].x; yy += Ck[d - 1].y; }
            m2x = (m2x + yx) + bb.x;
            m2y = (m2y + yy) + bb.y;
            if (m2x > 0.5f) { scx += 1.f; m2x = 0.f; }
            if (m2y > 0.5f) { scy += 1.f; m2y = 0.f; }
        }
        float2 res = make_float2(scx * 0.0625f, scy * 0.0625f);
        *(float2*)&out[(size_t)(r0 + w) * OUT_DIM + o_base + o2] = res;
    }
}

// ---------------------------------------------------------------------------
extern "C" void kernel_launch(void* const* d_in, const int* in_sizes, int n_in,
                              void* d_out, int out_size)
{
    const float* x  = (const float*)d_in[0];
    const float* W1 = (const float*)d_in[1];
    const float* b1 = (const float*)d_in[2];
    const float* W2 = (const float*)d_in[3];
    const float* b2 = (const float*)d_in[4];
    float* out = (float*)d_out;

    const int M = in_sizes[0] / IN_DIM;  // 32768

    dim3 g1(M / 128, HID / 256);
    gemm1_kernel<<<g1, 256>>>(x, W1, b1);

    bucketize_kernel<<<M / BK_ROWS, 512>>>();

    cudaFuncSetAttribute(phase2_kernel,
                         cudaFuncAttributeMaxDynamicSharedMemorySize,
                         P2_SMEM_BYTES);
    dim3 g2(M / ROWS_PER_BLOCK, OUT_DIM / 64);
    phase2_kernel<<<g2, 1024, P2_SMEM_BYTES>>>(W2, b2, out);
}